// round 16
// baseline (speedup 1.0000x reference)
#include <cuda_runtime.h>

#define NBATCH 64
#define NPTS   4096
#define NV4    32                  // 128 channels = 32 float4
#define NSL    32                  // slices per batch
#define PPS    (NPTS / NSL)        // 128 points per slice/CTA
#define PPWARP 16                  // points per warp (8 warps/CTA)

#define GB      32                 // batches per group-chain (64 MB of x)
#define NGROUPS (NBATCH / GB)      // 2

// scratch (device globals; no allocation)
__device__ float4 g_part [NBATCH * NSL * NV4];
__device__ float4 g_mean [NBATCH * NV4];
__device__ float  g_sc   [NBATCH * 16];
__device__ float4 g_scr4 [NBATCH * NPTS];        // {s, s*alpha, c, dbt*i1b}
__device__ float  g_scrq [NBATCH * NPTS];        // sqrt(t2 + dbt^2 * K)
__device__ float4 g_coef [NBATCH * NPTS];        // {A, Bm, Cb, De}
__device__ float  g_vpart[NBATCH * NSL];

__device__ __forceinline__ float dot4(float4 a, float4 b) {
    return a.x * b.x + a.y * b.y + a.z * b.z + a.w * b.w;
}
__device__ __forceinline__ float warpsum(float v) {
    #pragma unroll
    for (int o = 16; o > 0; o >>= 1) v += __shfl_xor_sync(0xffffffffu, v, o);
    return v;
}

// ---------------- K1: per-slice channel sums ----------------
__global__ __launch_bounds__(256)
void k1_sums(const float* __restrict__ x, int b0) {
    const int b = b0 + (blockIdx.x >> 5), sl = blockIdx.x & 31;
    const int warp = threadIdx.x >> 5, lane = threadIdx.x & 31;
    const float4* __restrict__ xb = (const float4*)x + (size_t)b * NPTS * NV4;
    const int base = sl * PPS + warp * PPWARP;

    float4 acc = make_float4(0.f, 0.f, 0.f, 0.f);
    #pragma unroll 4
    for (int k = 0; k < PPWARP; ++k) {
        float4 v = xb[(size_t)(base + k) * NV4 + lane];
        acc.x += v.x; acc.y += v.y; acc.z += v.z; acc.w += v.w;
    }
    __shared__ float4 sr[256];
    sr[threadIdx.x] = acc;
    __syncthreads();
    #pragma unroll
    for (int off = 128; off >= 32; off >>= 1) {
        if (threadIdx.x < off) {
            float4 a = sr[threadIdx.x], c = sr[threadIdx.x + off];
            a.x += c.x; a.y += c.y; a.z += c.z; a.w += c.w;
            sr[threadIdx.x] = a;
        }
        __syncthreads();
    }
    if (threadIdx.x < 32) g_part[(b * NSL + sl) * NV4 + lane] = sr[lane];
}

// ---------------- K2: mean + per-batch scalars ----------------
__global__ __launch_bounds__(32)
void k2_mean(const float* __restrict__ beta, int b0) {
    const int b = b0 + blockIdx.x, lane = threadIdx.x;
    const float4 beta4 = ((const float4*)beta)[lane];

    float4 m = make_float4(0.f, 0.f, 0.f, 0.f);
    for (int s = 0; s < NSL; ++s) {
        float4 p = g_part[(b * NSL + s) * NV4 + lane];
        m.x += p.x; m.y += p.y; m.z += p.z; m.w += p.w;
    }
    const float invN = 1.0f / NPTS;
    m.x *= invN; m.y *= invN; m.z *= invN; m.w *= invN;

    float d     = warpsum(dot4(m, m));
    float m0raw = __shfl_sync(0xffffffffu, m.x, 0);
    float neg   = fmaxf(2.f * m0raw * m0raw - d, 1e-8f);   // -linner(m,m)
    float inv   = rsqrtf(neg);
    float4 mean = make_float4(m.x * inv, m.y * inv, m.z * inv, m.w * inv);
    g_mean[b * NV4 + lane] = mean;

    float dmm = warpsum(dot4(mean, mean));
    float dbm = warpsum(dot4(beta4, mean));
    float dbb = warpsum(dot4(beta4, beta4));
    float mean0 = __shfl_sync(0xffffffffu, mean.x, 0);
    if (lane == 0) {
        float bb0 = beta4.x;
        float i1b = 1.f / (1.f + bb0);
        float nbb = dbb + 2.f * bb0 + 1.f;     // dot(beta+e0, beta+e0)
        float bp1 = bb0 + 1.f;
        float* sc = g_sc + b * 16;
        sc[0] = mean0;
        sc[1] = 1.f / (1.f + mean0);
        sc[2] = dmm;
        sc[3] = dmm + 2.f * mean0 + 1.f;   // dot(mean+e0, mean+e0)
        sc[4] = dbm;
        sc[5] = dbm + bb0;                 // dot(beta, mean+e0)
        sc[6] = bb0;
        sc[7] = i1b;
        sc[8] = nbb;
        // K: linner(f,f) = g^2 * (t2 + dbt^2 * K)
        sc[9] = 2.f * i1b + i1b * i1b * (nbb - 2.f * bp1 * bp1);
    }
}

// ---------------- K3: tangent scalars, 8-lane-per-point layout ----------------
__global__ __launch_bounds__(256)
void k3_tangent(const float* __restrict__ x, const float* __restrict__ beta, int b0) {
    const int b = b0 + (blockIdx.x >> 5), sl = blockIdx.x & 31;
    const int tid = threadIdx.x, warp = tid >> 5, lane = tid & 31;
    const int sub = lane & 7;                 // lane within 8-lane point-group
    const float4* __restrict__ xb = (const float4*)x + (size_t)b * NPTS * NV4;

    __shared__ float4 s_mean[32];
    __shared__ float4 s_beta[32];
    __shared__ float  s_nacc[8];

    if (tid < 32) {
        s_mean[tid] = g_mean[b * NV4 + tid];
        s_beta[tid] = ((const float4*)beta)[tid];
    }
    __syncthreads();

    const float* sc = g_sc + b * 16;
    const float mean0 = sc[0], i1m = sc[1], dmm = sc[2], emem = sc[3];
    const float dbm   = sc[4], dbe = sc[5], i1b = sc[7], Kb = sc[9];

    const int base = sl * PPS + warp * PPWARP;
    float nacc = 0.f;

    #pragma unroll
    for (int it = 0; it < PPWARP; it += 4) {
        const int p = base + it + (lane >> 3);          // group's point
        const float4* __restrict__ vp = xb + (size_t)p * NV4;

        float dxx = 0.f, dxm = 0.f, dbx = 0.f, x0loc = 0.f;
        #pragma unroll
        for (int i = 0; i < 4; ++i) {
            float4 v  = vp[sub + i * 8];
            if (i == 0 && sub == 0) x0loc = v.x;
            float4 mm = s_mean[sub + i * 8];
            float4 bb = s_beta[sub + i * 8];
            dxx += dot4(v, v);
            dxm += dot4(v, mm);
            dbx += dot4(v, bb);
        }
        // 3-round butterfly within each 8-lane group (independent across groups)
        #pragma unroll
        for (int o = 4; o > 0; o >>= 1) {
            dxx += __shfl_xor_sync(0xffffffffu, dxx, o);
            dxm += __shfl_xor_sync(0xffffffffu, dxm, o);
            dbx += __shfl_xor_sync(0xffffffffu, dbx, o);
        }
        const float x0 = __shfl_sync(0xffffffffu, x0loc, 0, 8);  // group broadcast

        float alpha = fmaxf(2.f * mean0 * x0 - dxm, 1.f + 1e-7f);
        float duu   = dxx - 2.f * alpha * dxm + alpha * alpha * dmm;  // dot(u,u)
        float u0    = x0 - alpha * mean0;
        float linuu = fmaxf(duu - 2.f * u0 * u0, 1e-8f);              // linner(u,u)
        float run   = rsqrtf(linuu);
        float ac    = __logf(alpha + sqrtf(fmaf(alpha, alpha, -1.f))); // acosh
        float s     = ac * run;
        float c     = s * u0 * i1m;
        float due   = dxm - alpha * dmm + u0;                         // dot(u, mean+e0)
        float t2    = fmaxf(s * s * duu - 2.f * s * c * due + c * c * emem, 0.f);
        float dbt   = s * (dbx - alpha * dbm) - c * dbe;              // dot(beta, x_T)
        float sq    = sqrtf(fmaxf(t2 + dbt * dbt * Kb, 0.f));
        nacc += sqrtf(t2);
        if (sub == 0) {
            const size_t o = (size_t)b * NPTS + p;
            g_scr4[o] = make_float4(s, s * alpha, c, dbt * i1b);
            g_scrq[o] = sq;
        }
    }

    // each point counted once: take sub==0 lane of each group
    float contrib = (sub == 0) ? nacc : 0.f;
    contrib = warpsum(contrib);
    if (lane == 0) s_nacc[warp] = contrib;
    __syncthreads();
    if (tid == 0) {
        float t = 0.f;
        #pragma unroll
        for (int i = 0; i < 8; ++i) t += s_nacc[i];
        g_vpart[b * NSL + sl] = t;
    }
}

// ---------------- K35: per-point output coefficients {A, Bm, Cb, De} --------
// out = A*x + Bm*mean + Cb*beta + De*e0
__global__ __launch_bounds__(256)
void k35_coef(const float* __restrict__ gamma, int b0) {
    const int b = b0 + (blockIdx.x >> 4), chunk = blockIdx.x & 15;
    const int tid = threadIdx.x;
    const int p = chunk * 256 + tid;

    __shared__ float s_g;
    if (tid == 0) {
        float vsum = 0.f;
        #pragma unroll
        for (int s = 0; s < NSL; ++s) vsum += g_vpart[b * NSL + s];
        s_g = gamma[0] / (vsum * (1.0f / NPTS) + 1e-5f);
    }
    __syncthreads();
    const float g = s_g;

    const size_t o = (size_t)b * NPTS + p;
    const float4 A4 = g_scr4[o];                 // {s, s*alpha, c, dbt*i1b}
    const float  sq = g_scrq[o];
    const float s = A4.x, sa = A4.y, c = A4.z, dbi = A4.w;

    const float pt  = g * dbi;                   // linner(beta,y)/(1+b0)
    const float nu  = fmaxf(g * sq, 1e-4f);      // sqrt(max(linner(f,f),1e-8))
    const float ex  = __expf(nu);
    const float ei  = __expf(-nu);
    const float ch  = 0.5f * (ex + ei);
    const float sh  = 0.5f * (ex - ei) * __fdividef(1.f, nu);  // sinh(nu)/nu

    // out = ch*beta + sh*( g*(s*x - sa*mean - c*(mean+e0)) + pt*(beta+e0) )
    float4 cf;
    cf.x = sh * g * s;                 // A  (coeff of x)
    cf.y = -sh * g * (sa + c);         // Bm (coeff of mean)
    cf.z = sh * pt + ch;               // Cb (coeff of beta)
    cf.w = sh * (pt - g * c);          // De (coeff of e0 -> channel 0)
    g_coef[o] = cf;
}

// ---------------- K4: pure affine stream ----------------
__global__ __launch_bounds__(256)
void k4_final(const float* __restrict__ x, const float* __restrict__ beta,
              float* __restrict__ out, int b0) {
    const int b = b0 + (blockIdx.x >> 5), sl = blockIdx.x & 31;
    const int warp = threadIdx.x >> 5, lane = threadIdx.x & 31;
    const float4* __restrict__ xb = (const float4*)x + (size_t)b * NPTS * NV4;
    float4* __restrict__ ob       = (float4*)out + (size_t)b * NPTS * NV4;

    const float4 mean4 = g_mean[b * NV4 + lane];
    const float4 beta4 = ((const float4*)beta)[lane];

    const int base = sl * PPS + warp * PPWARP;
    // one coalesced 256B load covers this warp's 16 points' coefficients
    const float4 cf = g_coef[(size_t)b * NPTS + base + (lane & 15)];

    #pragma unroll 4
    for (int k = 0; k < PPWARP; ++k) {
        const int p = base + k;
        const float A  = __shfl_sync(0xffffffffu, cf.x, k);
        const float Bm = __shfl_sync(0xffffffffu, cf.y, k);
        const float Cb = __shfl_sync(0xffffffffu, cf.z, k);
        const float De = __shfl_sync(0xffffffffu, cf.w, k);

        float4 v = __ldcs(&xb[(size_t)p * NV4 + lane]);   // last use: evict-first

        float4 o;
        o.x = A * v.x + Bm * mean4.x + Cb * beta4.x;
        o.y = A * v.y + Bm * mean4.y + Cb * beta4.y;
        o.z = A * v.z + Bm * mean4.z + Cb * beta4.z;
        o.w = A * v.w + Bm * mean4.w + Cb * beta4.w;
        if (lane == 0) o.x += De;                         // e0 -> channel 0

        __stcs(&ob[(size_t)p * NV4 + lane], o);           // streaming store
    }
}

extern "C" void kernel_launch(void* const* d_in, const int* in_sizes, int n_in,
                              void* d_out, int out_size) {
    const float* x     = (const float*)d_in[0];
    const float* beta  = (const float*)d_in[1];
    const float* gamma = (const float*)d_in[2];
    float* out = (float*)d_out;

    // Single-stream group chaining: each group of GB batches (64 MB of x)
    // runs k1->k2->k3->k35->k4 back-to-back so later passes re-read the
    // group's x from L2/L1 instead of DRAM.
    for (int grp = 0; grp < NGROUPS; ++grp) {
        const int b0 = grp * GB;
        k1_sums   <<<GB * NSL, 256>>>(x, b0);
        k2_mean   <<<GB,       32 >>>(beta, b0);
        k3_tangent<<<GB * NSL, 256>>>(x, beta, b0);
        k35_coef  <<<GB * 16,  256>>>(gamma, b0);
        k4_final  <<<GB * NSL, 256>>>(x, beta, out, b0);
    }
}